// round 3
// baseline (speedup 1.0000x reference)
#include <cuda_runtime.h>
#include <cstdint>
#include <cstddef>

#define BSZ  64
#define TT   512
#define FEAT 1024
#define HID  1024
#define H3   3072
#define NBLK 128
#define SWS  1028   // smem weight row stride (floats): (8g+c)*4 + k bank spread

// Scratch for x-projections: pre[m][n], m = b*T + t, n = gate*1024 + j
__device__ float g_pre[(size_t)BSZ * TT * H3];
// Per-step scratch: (r .* h) for the hbar matmul
__device__ float g_rh[(size_t)BSZ * HID];

// grid barrier state
__device__ unsigned g_count = 0;
__device__ volatile unsigned g_gen = 0;

// ---------- Blackwell packed f32x2 helpers ----------
__device__ __forceinline__ unsigned long long ffma2(unsigned long long a,
                                                    unsigned long long b,
                                                    unsigned long long c) {
    unsigned long long d;
    asm("fma.rn.f32x2 %0, %1, %2, %3;" : "=l"(d) : "l"(a), "l"(b), "l"(c));
    return d;
}
__device__ __forceinline__ unsigned long long pk2(float x) {
    unsigned long long r;
    asm("mov.b64 %0, {%1, %1};" : "=l"(r) : "f"(x));
    return r;
}
__device__ __forceinline__ float lo32(unsigned long long v) {
    return __uint_as_float((unsigned)(v & 0xffffffffull));
}
__device__ __forceinline__ float hi32(unsigned long long v) {
    return __uint_as_float((unsigned)(v >> 32));
}
__device__ __forceinline__ unsigned long long d2l(double d) {
    return __double_as_longlong(d);
}
__device__ __forceinline__ float sigmoidf_(float v) {
    return 1.0f / (1.0f + expf(-v));
}

// software grid sync for a co-resident grid of NBLK blocks
__device__ __forceinline__ void gsync() {
    __threadfence();            // order this thread's stores before arrival
    __syncthreads();
    if (threadIdx.x == 0) {
        unsigned my = g_gen;
        if (atomicAdd(&g_count, 1) == NBLK - 1) {
            g_count = 0;
            __threadfence();
            g_gen = my + 1;
        } else {
            while (g_gen == my) __nanosleep(32);
        }
        __threadfence();
    }
    __syncthreads();
}

// =====================================================================
// Kernel 1: x projections.  pre[m, n] = x[m,:] @ Wg_x[:, n%1024] + bias
// Tile: 64 (m) x 64 (n) x 32 (k).  f32x2 paired over N.
// =====================================================================
__global__ __launch_bounds__(256) void xproj_kernel(
    const float* __restrict__ x,
    const float* __restrict__ wz, const float* __restrict__ wr,
    const float* __restrict__ wh,
    const float* __restrict__ bz, const float* __restrict__ br,
    const float* __restrict__ bh)
{
    __shared__ float sx[64 * 68];   // [row][k]
    __shared__ float sw[32 * 68];   // [k][n]

    const int tid = threadIdx.x;
    const int n0  = blockIdx.x * 64;
    const int m0  = blockIdx.y * 64;

    const int gate = n0 >> 10;
    const int ng   = n0 & 1023;
    const float* wptr = (gate == 0) ? wz : (gate == 1) ? wr : wh;
    const float* bptr = (gate == 0) ? bz : (gate == 1) ? br : bh;

    const int c2 = tid & 15;
    const int mq = tid >> 4;

    unsigned long long acc[4][2];
#pragma unroll
    for (int u = 0; u < 4; u++) { acc[u][0] = 0ull; acc[u][1] = 0ull; }

    const int xs_kq  = tid & 7;
    const int xs_row = tid >> 3;
    const int ws_nq  = tid & 15;
    const int ws_kr  = tid >> 4;

    for (int k0 = 0; k0 < FEAT; k0 += 32) {
#pragma unroll
        for (int i = 0; i < 2; i++) {
            int row = xs_row + 32 * i;
            float4 v = *(const float4*)(x + (size_t)(m0 + row) * FEAT + k0 + 4 * xs_kq);
            *(float4*)&sx[row * 68 + 4 * xs_kq] = v;
        }
#pragma unroll
        for (int i = 0; i < 2; i++) {
            int kr = ws_kr + 16 * i;
            float4 v = *(const float4*)(wptr + (size_t)(1024 + k0 + kr) * HID + ng + 4 * ws_nq);
            *(float4*)&sw[kr * 68 + 4 * ws_nq] = v;
        }
        __syncthreads();

#pragma unroll
        for (int k = 0; k < 32; k += 4) {
            unsigned long long xp[4][4];
#pragma unroll
            for (int u = 0; u < 4; u++) {
                float4 xv = *(const float4*)&sx[(mq + 16 * u) * 68 + k];
                xp[u][0] = pk2(xv.x); xp[u][1] = pk2(xv.y);
                xp[u][2] = pk2(xv.z); xp[u][3] = pk2(xv.w);
            }
#pragma unroll
            for (int j = 0; j < 2; j++) {
                const int nn = 2 * c2 + 32 * j;
#pragma unroll
                for (int kk = 0; kk < 4; kk++) {
                    unsigned long long wv = d2l(*(const double*)&sw[(k + kk) * 68 + nn]);
#pragma unroll
                    for (int u = 0; u < 4; u++)
                        acc[u][j] = ffma2(xp[u][kk], wv, acc[u][j]);
                }
            }
        }
        __syncthreads();
    }

#pragma unroll
    for (int j = 0; j < 2; j++) {
        const int nn = 2 * c2 + 32 * j;
        const float b0 = bptr[ng + nn];
        const float b1 = bptr[ng + nn + 1];
#pragma unroll
        for (int u = 0; u < 4; u++) {
            const int m = m0 + mq + 16 * u;
            float2 r;
            r.x = lo32(acc[u][j]) + b0;
            r.y = hi32(acc[u][j]) + b1;
            *(float2*)&g_pre[(size_t)m * H3 + n0 + nn] = r;
        }
    }
}

// =====================================================================
// Kernel 2: persistent recurrence. 128 blocks, 8 h-columns each.
// Per step: phase A (z,r; writes rh) -> gsync -> phase B (hbar; writes
// out[:,t,:]) -> gsync.  Weights resident in smem for the whole kernel.
// =====================================================================
extern __shared__ float smem_dyn[];

__global__ __launch_bounds__(256) void recur_kernel(
    const float* __restrict__ h0,
    const float* __restrict__ wz, const float* __restrict__ wr,
    const float* __restrict__ wh,
    float* __restrict__ out)
{
    float* sw = smem_dyn;                 // [24][SWS] : (g*8+c) rows, k cols
    float* sh = smem_dyn + 24 * SWS;      // [64][68]  : staged h / rh chunk

    const int tid = threadIdx.x;
    const int j0  = blockIdx.x * 8;
    const int c   = tid & 7;
    const int bq  = tid >> 3;             // 0..31, rows bq and bq+32

    // ---- one-time: load this block's 24 weight columns, transposed ----
    for (int idx = tid; idx < 24 * 1024; idx += 256) {
        int r = idx >> 10;                // 0..23
        int k = idx & 1023;
        int g = r >> 3;
        const float* wg = (g == 0) ? wz : (g == 1) ? wr : wh;
        sw[r * SWS + k] = wg[(size_t)k * HID + j0 + (r & 7)];
    }
    __syncthreads();

    const int hs_kq = tid & 15;
    const int hs_r  = tid >> 4;

    for (int t = 0; t < TT; t++) {
        const float* hprev = (t == 0) ? h0 : (out + (size_t)(t - 1) * HID);
        const long   hstr  = (t == 0) ? (long)HID : (long)TT * HID;

        // ================= phase A: z, r gates =================
        unsigned long long accA[2][2];
#pragma unroll
        for (int u = 0; u < 2; u++) { accA[u][0] = 0ull; accA[u][1] = 0ull; }

        for (int k0 = 0; k0 < HID; k0 += 64) {
#pragma unroll
            for (int i = 0; i < 4; i++) {
                int r = hs_r + 16 * i;
                float4 v = *(const float4*)(hprev + (size_t)r * hstr + k0 + 4 * hs_kq);
                *(float4*)&sh[r * 68 + 4 * hs_kq] = v;
            }
            __syncthreads();

#pragma unroll
            for (int kk = 0; kk < 64; kk += 4) {
                const int k = k0 + kk;
                double2 hv0 = *(const double2*)&sh[bq * 68 + kk];
                double2 hv1 = *(const double2*)&sh[(bq + 32) * 68 + kk];
#pragma unroll
                for (int g = 0; g < 2; g++) {
                    double2 wv = *(const double2*)&sw[(g * 8 + c) * SWS + k];
                    accA[0][g] = ffma2(d2l(hv0.x), d2l(wv.x), accA[0][g]);
                    accA[0][g] = ffma2(d2l(hv0.y), d2l(wv.y), accA[0][g]);
                    accA[1][g] = ffma2(d2l(hv1.x), d2l(wv.x), accA[1][g]);
                    accA[1][g] = ffma2(d2l(hv1.y), d2l(wv.y), accA[1][g]);
                }
            }
            __syncthreads();
        }

        float zreg[2], hpreg[2];
#pragma unroll
        for (int u = 0; u < 2; u++) {
            const int b = bq + 32 * u;
            const float sz = lo32(accA[u][0]) + hi32(accA[u][0]);
            const float sr = lo32(accA[u][1]) + hi32(accA[u][1]);

            const float* p = g_pre + (size_t)(b * TT + t) * H3 + j0 + c;
            const float xz = p[0];
            const float xr = p[1024];

            const float z  = sigmoidf_(sz + xz);
            const float r  = sigmoidf_(sr + xr);
            const float hp = __ldg(hprev + (size_t)b * hstr + j0 + c);

            zreg[u]  = z;
            hpreg[u] = hp;
            g_rh[(size_t)b * HID + j0 + c] = r * hp;
        }

        gsync();   // rh complete

        // ================= phase B: hbar + update =================
        unsigned long long accB[2] = {0ull, 0ull};

        for (int k0 = 0; k0 < HID; k0 += 64) {
#pragma unroll
            for (int i = 0; i < 4; i++) {
                int r = hs_r + 16 * i;
                // g_rh addresses are reused every step -> bypass L1
                float4 v = __ldcg((const float4*)(g_rh + (size_t)r * HID + k0 + 4 * hs_kq));
                *(float4*)&sh[r * 68 + 4 * hs_kq] = v;
            }
            __syncthreads();

#pragma unroll
            for (int kk = 0; kk < 64; kk += 4) {
                const int k = k0 + kk;
                double2 hv0 = *(const double2*)&sh[bq * 68 + kk];
                double2 hv1 = *(const double2*)&sh[(bq + 32) * 68 + kk];
                double2 wv  = *(const double2*)&sw[(16 + c) * SWS + k];
                accB[0] = ffma2(d2l(hv0.x), d2l(wv.x), accB[0]);
                accB[0] = ffma2(d2l(hv0.y), d2l(wv.y), accB[0]);
                accB[1] = ffma2(d2l(hv1.x), d2l(wv.x), accB[1]);
                accB[1] = ffma2(d2l(hv1.y), d2l(wv.y), accB[1]);
            }
            __syncthreads();
        }

#pragma unroll
        for (int u = 0; u < 2; u++) {
            const int b = bq + 32 * u;
            const float sg = lo32(accB[u]) + hi32(accB[u]);
            const float xh = g_pre[(size_t)(b * TT + t) * H3 + 2048 + j0 + c];

            const float hb = tanhf(sg + xh);
            const float hn = (1.0f - zreg[u]) * hpreg[u] + zreg[u] * hb;

            out[((size_t)b * TT + t) * HID + j0 + c] = hn;
            if (t == TT - 1)
                out[(size_t)BSZ * TT * HID + (size_t)b * HID + j0 + c] = hn;
        }

        gsync();   // out[:,t,:] complete before next step reads it
    }
}

// =====================================================================
extern "C" void kernel_launch(void* const* d_in, const int* in_sizes, int n_in,
                              void* d_out, int out_size)
{
    const float* x  = (const float*)d_in[0];
    const float* h0 = (const float*)d_in[1];
    const float* wz = (const float*)d_in[2];
    const float* wr = (const float*)d_in[3];
    const float* wh = (const float*)d_in[4];
    const float* bz = (const float*)d_in[5];
    const float* br = (const float*)d_in[6];
    const float* bh = (const float*)d_in[7];
    float* out = (float*)d_out;

    dim3 g1(H3 / 64, (BSZ * TT) / 64);
    xproj_kernel<<<g1, 256>>>(x, wz, wr, wh, bz, br, bh);

    const int smem_bytes = (24 * SWS + 64 * 68) * sizeof(float);
    static bool attr_set = false;
    if (!attr_set) {
        cudaFuncSetAttribute(recur_kernel,
                             cudaFuncAttributeMaxDynamicSharedMemorySize,
                             smem_bytes);
        attr_set = true;
    }
    recur_kernel<<<NBLK, 256, smem_bytes>>>(h0, wz, wr, wh, out);
}